// round 1
// baseline (speedup 1.0000x reference)
#include <cuda_runtime.h>
#include <cuda_bf16.h>
#include <math.h>

// Problem constants
#define BATCH  2
#define TSEQ   2048
#define CDIM   512
#define NHEAD  16
#define HS     32
#define DFF    2048
#define MROWS  (BATCH * TSEQ)   // 4096
#define LN_EPS 1e-3f

// Scratch: h1,q,k,v,o,x1,h2 (7 x 2M floats) + f1 (8M floats) = 23068672 floats (88MB)
__device__ float g_scratch[23068672];

// ----------------------------------------------------------------------------
// LayerNorm: one block per row (C=512), 128 threads, float4 per thread
// ----------------------------------------------------------------------------
__global__ void ln_kernel(const float* __restrict__ x, const float* __restrict__ g,
                          const float* __restrict__ b, float* __restrict__ out) {
    __shared__ float sh[4];
    const int row = blockIdx.x;
    const int t = threadIdx.x;           // 0..127
    const float4 v = reinterpret_cast<const float4*>(x + (size_t)row * CDIM)[t];

    // mean
    float s = v.x + v.y + v.z + v.w;
    #pragma unroll
    for (int o = 16; o > 0; o >>= 1) s += __shfl_xor_sync(0xffffffffu, s, o);
    if ((t & 31) == 0) sh[t >> 5] = s;
    __syncthreads();
    const float mu = (sh[0] + sh[1] + sh[2] + sh[3]) * (1.0f / CDIM);
    __syncthreads();

    // variance
    float d0 = v.x - mu, d1 = v.y - mu, d2 = v.z - mu, d3 = v.w - mu;
    float q = d0*d0 + d1*d1 + d2*d2 + d3*d3;
    #pragma unroll
    for (int o = 16; o > 0; o >>= 1) q += __shfl_xor_sync(0xffffffffu, q, o);
    if ((t & 31) == 0) sh[t >> 5] = q;
    __syncthreads();
    const float var = (sh[0] + sh[1] + sh[2] + sh[3]) * (1.0f / CDIM);
    const float inv = rsqrtf(var + LN_EPS);

    const float4 gv = reinterpret_cast<const float4*>(g)[t];
    const float4 bv = reinterpret_cast<const float4*>(b)[t];
    float4 o4;
    o4.x = d0 * inv * gv.x + bv.x;
    o4.y = d1 * inv * gv.y + bv.y;
    o4.z = d2 * inv * gv.z + bv.z;
    o4.w = d3 * inv * gv.w + bv.w;
    reinterpret_cast<float4*>(out + (size_t)row * CDIM)[t] = o4;
}

// ----------------------------------------------------------------------------
// Tiled SGEMM: out[M,N] = A[M,K] @ W + bias (+res) (relu?)
// HEADED: W stored as [N/32][K][32] (per-head (H,C,HS) weights), else [K,N].
// 64x64 tile, BK=16, 256 threads, 4x4 microtile.
// Requires M%64==0, N%64==0, K%16==0.
// ----------------------------------------------------------------------------
template<int HEADED, int RELU, int HASRES>
__global__ void sgemm_kernel(const float* __restrict__ A, const float* __restrict__ W,
                             const float* __restrict__ bias, const float* __restrict__ res,
                             float* __restrict__ out, int M, int N, int K) {
    __shared__ float As[16][64];
    __shared__ float Bs[16][64];
    const int tid = threadIdx.x;
    const int tx = tid & 15, ty = tid >> 4;
    const int m0 = blockIdx.y * 64, n0 = blockIdx.x * 64;
    const int am = tid >> 2, ak = (tid & 3) << 2;
    const int bk = tid >> 4, bn = (tid & 15) << 2;

    float acc[4][4];
    #pragma unroll
    for (int i = 0; i < 4; i++)
        #pragma unroll
        for (int j = 0; j < 4; j++) acc[i][j] = 0.0f;

    for (int kk = 0; kk < K; kk += 16) {
        const float4 av = *reinterpret_cast<const float4*>(A + (size_t)(m0 + am) * K + kk + ak);
        As[ak + 0][am] = av.x;
        As[ak + 1][am] = av.y;
        As[ak + 2][am] = av.z;
        As[ak + 3][am] = av.w;

        float4 bv;
        if (HEADED) {
            const int ng = n0 + bn;
            bv = *reinterpret_cast<const float4*>(
                W + (size_t)(ng >> 5) * ((size_t)K * 32) + (size_t)(kk + bk) * 32 + (ng & 31));
        } else {
            bv = *reinterpret_cast<const float4*>(W + (size_t)(kk + bk) * N + n0 + bn);
        }
        *reinterpret_cast<float4*>(&Bs[bk][bn]) = bv;
        __syncthreads();

        #pragma unroll
        for (int k = 0; k < 16; k++) {
            const float4 a = *reinterpret_cast<const float4*>(&As[k][ty << 2]);
            const float4 bb = *reinterpret_cast<const float4*>(&Bs[k][tx << 2]);
            const float ar[4] = {a.x, a.y, a.z, a.w};
            const float br[4] = {bb.x, bb.y, bb.z, bb.w};
            #pragma unroll
            for (int i = 0; i < 4; i++)
                #pragma unroll
                for (int j = 0; j < 4; j++)
                    acc[i][j] += ar[i] * br[j];
        }
        __syncthreads();
    }

    #pragma unroll
    for (int i = 0; i < 4; i++) {
        const int row = m0 + (ty << 2) + i;
        #pragma unroll
        for (int j = 0; j < 4; j++) {
            const int col = n0 + (tx << 2) + j;
            float v = acc[i][j] + bias[col];
            if (HASRES) v += res[(size_t)row * N + col];
            if (RELU) v = fmaxf(v, 0.0f);
            out[(size_t)row * N + col] = v;
        }
    }
}

// ----------------------------------------------------------------------------
// Causal flash attention, NO 1/sqrt(hs) scaling (per reference).
// Q/K/V/O layout: [B*T, 512] with column = h*32 + d.
// One warp per query row; 8 warps per block; 64-key smem tiles.
// Grid: (B*NHEAD, TSEQ/8), 256 threads.
// ----------------------------------------------------------------------------
__global__ void attn_kernel(const float* __restrict__ Q, const float* __restrict__ K,
                            const float* __restrict__ V, float* __restrict__ O) {
    __shared__ float ksh[64][HS + 1];
    __shared__ float vsh[64][HS + 1];
    const int bh = blockIdx.x;
    const int b = bh / NHEAD, h = bh % NHEAD;
    const int warp = threadIdx.x >> 5;
    const int lane = threadIdx.x & 31;
    const int row = blockIdx.y * 8 + warp;
    const int rowMax = blockIdx.y * 8 + 7;

    const float qr = Q[(size_t)(b * TSEQ + row) * CDIM + h * HS + lane];

    float m = -INFINITY, l = 0.0f, oacc = 0.0f;

    for (int j0 = 0; j0 <= rowMax; j0 += 64) {
        __syncthreads();
        // cooperative tile load: 64 keys x 32 dims for K and V
        #pragma unroll
        for (int i = 0; i < 8; i++) {
            const int linear = i * 256 + threadIdx.x;
            const int j = linear >> 5, d = linear & 31;
            const size_t gidx = (size_t)(b * TSEQ + j0 + j) * CDIM + h * HS + d;
            ksh[j][d] = K[gidx];
            vsh[j][d] = V[gidx];
        }
        __syncthreads();

        #pragma unroll
        for (int sub = 0; sub < 64; sub += 32) {
            const int jbase = j0 + sub;
            if (jbase > row) break;
            const int key = jbase + lane;

            // score for this lane's key
            float sacc = 0.0f;
            #pragma unroll
            for (int d = 0; d < 32; d++) {
                const float qd = __shfl_sync(0xffffffffu, qr, d);
                sacc += qd * ksh[sub + lane][d];
            }
            const float s = (key <= row) ? sacc : -INFINITY;

            // online softmax
            float mx = s;
            #pragma unroll
            for (int o = 16; o > 0; o >>= 1) mx = fmaxf(mx, __shfl_xor_sync(0xffffffffu, mx, o));
            const float mnew = fmaxf(m, mx);
            const float scale = __expf(m - mnew);     // 0 on first chunk (m=-inf)
            const float p = __expf(s - mnew);         // 0 for masked lanes
            float ps = p;
            #pragma unroll
            for (int o = 16; o > 0; o >>= 1) ps += __shfl_xor_sync(0xffffffffu, ps, o);
            l = l * scale + ps;
            oacc *= scale;
            #pragma unroll
            for (int j = 0; j < 32; j++) {
                const float pj = __shfl_sync(0xffffffffu, p, j);
                oacc += pj * vsh[sub + j][lane];
            }
            m = mnew;
        }
    }

    O[(size_t)(b * TSEQ + row) * CDIM + h * HS + lane] = oacc / l;
}

// ----------------------------------------------------------------------------
// Launch
// ----------------------------------------------------------------------------
extern "C" void kernel_launch(void* const* d_in, const int* in_sizes, int n_in,
                              void* d_out, int out_size) {
    const float* x   = (const float*)d_in[0];
    const float* Wq  = (const float*)d_in[1];
    const float* bq  = (const float*)d_in[2];
    const float* Wk  = (const float*)d_in[3];
    const float* bk  = (const float*)d_in[4];
    const float* Wv  = (const float*)d_in[5];
    const float* bv  = (const float*)d_in[6];
    const float* Wo  = (const float*)d_in[7];
    const float* bo  = (const float*)d_in[8];
    const float* W1  = (const float*)d_in[9];
    const float* b1  = (const float*)d_in[10];
    const float* W2  = (const float*)d_in[11];
    const float* b2  = (const float*)d_in[12];
    const float* g1  = (const float*)d_in[13];
    const float* be1 = (const float*)d_in[14];
    const float* g2  = (const float*)d_in[15];
    const float* be2 = (const float*)d_in[16];
    float* out = (float*)d_out;

    float* base = nullptr;
    cudaGetSymbolAddress((void**)&base, g_scratch);
    const size_t SZ = (size_t)MROWS * CDIM;  // 2M floats
    float* h1  = base + 0 * SZ;
    float* qb  = base + 1 * SZ;
    float* kb  = base + 2 * SZ;
    float* vb  = base + 3 * SZ;
    float* ob  = base + 4 * SZ;
    float* x1  = base + 5 * SZ;
    float* h2  = base + 6 * SZ;
    float* f1  = base + 7 * SZ;  // 4096 x 2048

    const dim3 g_cc(CDIM / 64, MROWS / 64);   // (8, 64)
    const dim3 g_cf(DFF / 64, MROWS / 64);    // (32, 64)

    // 1. pre-LN (attention)
    ln_kernel<<<MROWS, 128>>>(x, g1, be1, h1);
    // 2-4. Q,K,V projections (headed weight layout [H][C][HS])
    sgemm_kernel<1, 0, 0><<<g_cc, 256>>>(h1, Wq, bq, nullptr, qb, MROWS, CDIM, CDIM);
    sgemm_kernel<1, 0, 0><<<g_cc, 256>>>(h1, Wk, bk, nullptr, kb, MROWS, CDIM, CDIM);
    sgemm_kernel<1, 0, 0><<<g_cc, 256>>>(h1, Wv, bv, nullptr, vb, MROWS, CDIM, CDIM);
    // 5. causal attention (no score scaling)
    attn_kernel<<<dim3(BATCH * NHEAD, TSEQ / 8), 256>>>(qb, kb, vb, ob);
    // 6. output projection + residual
    sgemm_kernel<0, 0, 1><<<g_cc, 256>>>(ob, Wo, bo, x, x1, MROWS, CDIM, CDIM);
    // 7. pre-LN (FFN)
    ln_kernel<<<MROWS, 128>>>(x1, g2, be2, h2);
    // 8. FFN up + ReLU
    sgemm_kernel<0, 1, 0><<<g_cf, 256>>>(h2, W1, b1, nullptr, f1, MROWS, DFF, CDIM);
    // 9. FFN down + residual -> output
    sgemm_kernel<0, 0, 1><<<g_cc, 256>>>(f1, W2, b2, x1, out, MROWS, CDIM, DFF);
}

// round 2
// speedup vs baseline: 4.7773x; 4.7773x over previous
#include <cuda_runtime.h>
#include <cuda_bf16.h>
#include <math.h>

// Problem constants
#define BATCH  2
#define TSEQ   2048
#define CDIM   512
#define NHEAD  16
#define HS     32
#define DFF    2048
#define MROWS  (BATCH * TSEQ)   // 4096
#define LN_EPS 1e-3f

// Scratch: h1,q,k,v,o,x1,h2 (7 x 2M floats) + f1 (8M floats)
__device__ float g_scratch[23068672];

__device__ __forceinline__ unsigned f2tf(float f) {
    unsigned u;
    asm("cvt.rna.tf32.f32 %0, %1;" : "=r"(u) : "f"(f));
    return u;
}

__device__ __forceinline__ void mma_tf32(float* c, const unsigned* a, unsigned b0, unsigned b1) {
    asm volatile("mma.sync.aligned.m16n8k8.row.col.f32.tf32.tf32.f32 "
                 "{%0,%1,%2,%3}, {%4,%5,%6,%7}, {%8,%9}, {%0,%1,%2,%3};"
                 : "+f"(c[0]), "+f"(c[1]), "+f"(c[2]), "+f"(c[3])
                 : "r"(a[0]), "r"(a[1]), "r"(a[2]), "r"(a[3]), "r"(b0), "r"(b1));
}

// ----------------------------------------------------------------------------
// LayerNorm: one block per row (C=512), 128 threads, float4 per thread
// ----------------------------------------------------------------------------
__global__ void ln_kernel(const float* __restrict__ x, const float* __restrict__ g,
                          const float* __restrict__ b, float* __restrict__ out) {
    __shared__ float sh[4];
    const int row = blockIdx.x;
    const int t = threadIdx.x;
    const float4 v = reinterpret_cast<const float4*>(x + (size_t)row * CDIM)[t];

    float s = v.x + v.y + v.z + v.w;
    #pragma unroll
    for (int o = 16; o > 0; o >>= 1) s += __shfl_xor_sync(0xffffffffu, s, o);
    if ((t & 31) == 0) sh[t >> 5] = s;
    __syncthreads();
    const float mu = (sh[0] + sh[1] + sh[2] + sh[3]) * (1.0f / CDIM);
    __syncthreads();

    float d0 = v.x - mu, d1 = v.y - mu, d2 = v.z - mu, d3 = v.w - mu;
    float q = d0*d0 + d1*d1 + d2*d2 + d3*d3;
    #pragma unroll
    for (int o = 16; o > 0; o >>= 1) q += __shfl_xor_sync(0xffffffffu, q, o);
    if ((t & 31) == 0) sh[t >> 5] = q;
    __syncthreads();
    const float var = (sh[0] + sh[1] + sh[2] + sh[3]) * (1.0f / CDIM);
    const float inv = rsqrtf(var + LN_EPS);

    const float4 gv = reinterpret_cast<const float4*>(g)[t];
    const float4 bv = reinterpret_cast<const float4*>(b)[t];
    float4 o4;
    o4.x = d0 * inv * gv.x + bv.x;
    o4.y = d1 * inv * gv.y + bv.y;
    o4.z = d2 * inv * gv.z + bv.z;
    o4.w = d3 * inv * gv.w + bv.w;
    reinterpret_cast<float4*>(out + (size_t)row * CDIM)[t] = o4;
}

// ----------------------------------------------------------------------------
// tf32 tensor-core GEMM: out[M,N] = A[M,K] @ W + bias (+res) (relu?)
// HEADED: W as [N/32][K][32] (per-head (H,C,HS)), else [K,N].
// BM=128, BN=128, BK=16; 256 threads = 8 warps (2m x 4n); warp = 64x32;
// mma m16n8k8: 4x4 tiles per warp. Smem stride 136 -> conflict-free frag LDS.
// ----------------------------------------------------------------------------
#define ASTR 136
#define BSTR 136

template<int HEADED, int RELU, int HASRES>
__global__ __launch_bounds__(256, 2)
void gemm_tc(const float* __restrict__ A, const float* __restrict__ W,
             const float* __restrict__ bias, const float* __restrict__ res,
             float* __restrict__ out, int M, int N, int K) {
    __shared__ unsigned As[16][ASTR];   // [k][m]
    __shared__ unsigned Bs[16][BSTR];   // [k][n]
    const int tid  = threadIdx.x;
    const int lane = tid & 31;
    const int warp = tid >> 5;
    const int wm = (warp & 1) * 64;
    const int wn = (warp >> 1) * 32;
    const int m0 = blockIdx.y * 128;
    const int n0 = blockIdx.x * 128;
    const int r  = lane >> 2, cq = lane & 3;

    const int arow = tid >> 2;           // 0..63  (rows arow, arow+64)
    const int acol = (tid & 3) << 2;     // k offset, float4
    const int brow = tid >> 5;           // 0..7   (rows brow, brow+8)
    const int bcol = (tid & 31) << 2;    // n offset, float4

    float acc[4][4][4];
    #pragma unroll
    for (int i = 0; i < 4; i++)
        #pragma unroll
        for (int j = 0; j < 4; j++) {
            acc[i][j][0] = 0.f; acc[i][j][1] = 0.f; acc[i][j][2] = 0.f; acc[i][j][3] = 0.f;
        }

    const float* Aptr = A + (size_t)(m0 + arow) * K + acol;
    const int n_g = n0 + bcol;
    const size_t brs = HEADED ? 32 : (size_t)N;
    const float* Bptr = HEADED
        ? (W + (size_t)(n_g >> 5) * ((size_t)K * 32) + (n_g & 31))
        : (W + n_g);

    float4 a0r = *reinterpret_cast<const float4*>(Aptr);
    float4 a1r = *reinterpret_cast<const float4*>(Aptr + (size_t)64 * K);
    float4 b0r = *reinterpret_cast<const float4*>(Bptr + (size_t)brow * brs);
    float4 b1r = *reinterpret_cast<const float4*>(Bptr + (size_t)(brow + 8) * brs);

    for (int kk = 0; kk < K; kk += 16) {
        __syncthreads();
        As[acol + 0][arow] = f2tf(a0r.x);
        As[acol + 1][arow] = f2tf(a0r.y);
        As[acol + 2][arow] = f2tf(a0r.z);
        As[acol + 3][arow] = f2tf(a0r.w);
        As[acol + 0][arow + 64] = f2tf(a1r.x);
        As[acol + 1][arow + 64] = f2tf(a1r.y);
        As[acol + 2][arow + 64] = f2tf(a1r.z);
        As[acol + 3][arow + 64] = f2tf(a1r.w);
        Bs[brow][bcol + 0] = f2tf(b0r.x);
        Bs[brow][bcol + 1] = f2tf(b0r.y);
        Bs[brow][bcol + 2] = f2tf(b0r.z);
        Bs[brow][bcol + 3] = f2tf(b0r.w);
        Bs[brow + 8][bcol + 0] = f2tf(b1r.x);
        Bs[brow + 8][bcol + 1] = f2tf(b1r.y);
        Bs[brow + 8][bcol + 2] = f2tf(b1r.z);
        Bs[brow + 8][bcol + 3] = f2tf(b1r.w);
        __syncthreads();

        if (kk + 16 < K) {
            a0r = *reinterpret_cast<const float4*>(Aptr + kk + 16);
            a1r = *reinterpret_cast<const float4*>(Aptr + (size_t)64 * K + kk + 16);
            b0r = *reinterpret_cast<const float4*>(Bptr + (size_t)(kk + 16 + brow) * brs);
            b1r = *reinterpret_cast<const float4*>(Bptr + (size_t)(kk + 16 + brow + 8) * brs);
        }

        #pragma unroll
        for (int ks = 0; ks < 2; ks++) {
            const int k = ks * 8 + cq;
            unsigned af[4][4], bf[4][2];
            #pragma unroll
            for (int mt = 0; mt < 4; mt++) {
                const int m = wm + mt * 16 + r;
                af[mt][0] = As[k][m];
                af[mt][1] = As[k][m + 8];
                af[mt][2] = As[k + 4][m];
                af[mt][3] = As[k + 4][m + 8];
            }
            #pragma unroll
            for (int nt = 0; nt < 4; nt++) {
                const int n = wn + nt * 8 + r;
                bf[nt][0] = Bs[k][n];
                bf[nt][1] = Bs[k + 4][n];
            }
            #pragma unroll
            for (int mt = 0; mt < 4; mt++)
                #pragma unroll
                for (int nt = 0; nt < 4; nt++)
                    mma_tf32(acc[mt][nt], af[mt], bf[nt][0], bf[nt][1]);
        }
    }

    #pragma unroll
    for (int mt = 0; mt < 4; mt++) {
        #pragma unroll
        for (int nt = 0; nt < 4; nt++) {
            const int row = m0 + wm + mt * 16 + r;
            const int col = n0 + wn + nt * 8 + (cq << 1);
            const float2 bb = *reinterpret_cast<const float2*>(bias + col);
            float v0 = acc[mt][nt][0] + bb.x;
            float v1 = acc[mt][nt][1] + bb.y;
            float v2 = acc[mt][nt][2] + bb.x;
            float v3 = acc[mt][nt][3] + bb.y;
            if (HASRES) {
                const float2 r0v = *reinterpret_cast<const float2*>(res + (size_t)row * N + col);
                const float2 r1v = *reinterpret_cast<const float2*>(res + (size_t)(row + 8) * N + col);
                v0 += r0v.x; v1 += r0v.y; v2 += r1v.x; v3 += r1v.y;
            }
            if (RELU) {
                v0 = fmaxf(v0, 0.f); v1 = fmaxf(v1, 0.f);
                v2 = fmaxf(v2, 0.f); v3 = fmaxf(v3, 0.f);
            }
            *reinterpret_cast<float2*>(out + (size_t)row * N + col) = make_float2(v0, v1);
            *reinterpret_cast<float2*>(out + (size_t)(row + 8) * N + col) = make_float2(v2, v3);
        }
    }
}

// ----------------------------------------------------------------------------
// Flash attention with tf32 mma. NO 1/sqrt(hs) scaling (per reference).
// Grid: (B*H, T/64); 128 threads = 4 warps, 16 query rows each.
// Key tiles of 64. S = Q K^T via mma; online softmax in C-frags;
// P routed through warp-private padded smem; O += P V via mma.
// ----------------------------------------------------------------------------
#define KSTR 36
#define PSTR 68

__global__ __launch_bounds__(128)
void attn_tc(const float* __restrict__ Q, const float* __restrict__ K,
             const float* __restrict__ V, float* __restrict__ O) {
    __shared__ unsigned Ksh[64][KSTR];
    __shared__ unsigned Vsh[64][KSTR];
    __shared__ unsigned Psh[4][16][PSTR];
    const int bh = blockIdx.x;
    const int b = bh >> 4, h = bh & 15;
    const int warp = threadIdx.x >> 5;
    const int lane = threadIdx.x & 31;
    const int qt = blockIdx.y;
    const int qbase = qt * 64 + warp * 16;
    const int r = lane >> 2, c = lane & 3;

    // Q fragments (A-frag, m16 x k32 -> 4 ksteps)
    unsigned qf[4][4];
    const float* Qb = Q + (size_t)(b * TSEQ + qbase) * CDIM + h * HS;
    #pragma unroll
    for (int ks = 0; ks < 4; ks++) {
        qf[ks][0] = f2tf(Qb[(size_t)r * CDIM + ks * 8 + c]);
        qf[ks][1] = f2tf(Qb[(size_t)(r + 8) * CDIM + ks * 8 + c]);
        qf[ks][2] = f2tf(Qb[(size_t)r * CDIM + ks * 8 + c + 4]);
        qf[ks][3] = f2tf(Qb[(size_t)(r + 8) * CDIM + ks * 8 + c + 4]);
    }

    float oacc[4][4];
    #pragma unroll
    for (int i = 0; i < 4; i++) { oacc[i][0]=0.f; oacc[i][1]=0.f; oacc[i][2]=0.f; oacc[i][3]=0.f; }
    float m0r = -INFINITY, m1r = -INFINITY, l0 = 0.f, l1 = 0.f;

    const int nTiles = qt + 1;
    for (int jt = 0; jt < nTiles; jt++) {
        const int j0 = jt * 64;
        __syncthreads();
        #pragma unroll
        for (int i = 0; i < 4; i++) {
            const int idx = i * 128 + threadIdx.x;   // 512 float4 slots
            const int row = idx >> 3;
            const int d4 = (idx & 7) << 2;
            const size_t g = (size_t)(b * TSEQ + j0 + row) * CDIM + h * HS + d4;
            const float4 kv = *reinterpret_cast<const float4*>(K + g);
            const float4 vv = *reinterpret_cast<const float4*>(V + g);
            Ksh[row][d4 + 0] = f2tf(kv.x); Ksh[row][d4 + 1] = f2tf(kv.y);
            Ksh[row][d4 + 2] = f2tf(kv.z); Ksh[row][d4 + 3] = f2tf(kv.w);
            Vsh[row][d4 + 0] = f2tf(vv.x); Vsh[row][d4 + 1] = f2tf(vv.y);
            Vsh[row][d4 + 2] = f2tf(vv.z); Vsh[row][d4 + 3] = f2tf(vv.w);
        }
        __syncthreads();

        if (j0 <= qbase + 15) {
            // S = Q K^T  (16 x 64)
            float s[8][4];
            #pragma unroll
            for (int nt = 0; nt < 8; nt++) { s[nt][0]=0.f; s[nt][1]=0.f; s[nt][2]=0.f; s[nt][3]=0.f; }
            #pragma unroll
            for (int ks = 0; ks < 4; ks++) {
                #pragma unroll
                for (int nt = 0; nt < 8; nt++) {
                    const unsigned kb0 = Ksh[nt * 8 + r][ks * 8 + c];
                    const unsigned kb1 = Ksh[nt * 8 + r][ks * 8 + c + 4];
                    mma_tf32(s[nt], qf[ks], kb0, kb1);
                }
            }
            // causal mask (only the diagonal tile needs it)
            if (j0 + 63 > qbase) {
                #pragma unroll
                for (int nt = 0; nt < 8; nt++) {
                    const int key = j0 + nt * 8 + (c << 1);
                    if (key     > qbase + r)     s[nt][0] = -INFINITY;
                    if (key + 1 > qbase + r)     s[nt][1] = -INFINITY;
                    if (key     > qbase + 8 + r) s[nt][2] = -INFINITY;
                    if (key + 1 > qbase + 8 + r) s[nt][3] = -INFINITY;
                }
            }
            // online softmax
            float mx0 = -INFINITY, mx1 = -INFINITY;
            #pragma unroll
            for (int nt = 0; nt < 8; nt++) {
                mx0 = fmaxf(mx0, fmaxf(s[nt][0], s[nt][1]));
                mx1 = fmaxf(mx1, fmaxf(s[nt][2], s[nt][3]));
            }
            mx0 = fmaxf(mx0, __shfl_xor_sync(0xffffffffu, mx0, 1));
            mx0 = fmaxf(mx0, __shfl_xor_sync(0xffffffffu, mx0, 2));
            mx1 = fmaxf(mx1, __shfl_xor_sync(0xffffffffu, mx1, 1));
            mx1 = fmaxf(mx1, __shfl_xor_sync(0xffffffffu, mx1, 2));
            const float mn0 = fmaxf(m0r, mx0);
            const float mn1 = fmaxf(m1r, mx1);
            const float sc0 = __expf(m0r - mn0);
            const float sc1 = __expf(m1r - mn1);
            float ps0 = 0.f, ps1 = 0.f;
            #pragma unroll
            for (int nt = 0; nt < 8; nt++) {
                const float p0 = __expf(s[nt][0] - mn0);
                const float p1 = __expf(s[nt][1] - mn0);
                const float p2 = __expf(s[nt][2] - mn1);
                const float p3 = __expf(s[nt][3] - mn1);
                ps0 += p0 + p1; ps1 += p2 + p3;
                Psh[warp][r][nt * 8 + (c << 1)]         = f2tf(p0);
                Psh[warp][r][nt * 8 + (c << 1) + 1]     = f2tf(p1);
                Psh[warp][r + 8][nt * 8 + (c << 1)]     = f2tf(p2);
                Psh[warp][r + 8][nt * 8 + (c << 1) + 1] = f2tf(p3);
            }
            ps0 += __shfl_xor_sync(0xffffffffu, ps0, 1);
            ps0 += __shfl_xor_sync(0xffffffffu, ps0, 2);
            ps1 += __shfl_xor_sync(0xffffffffu, ps1, 1);
            ps1 += __shfl_xor_sync(0xffffffffu, ps1, 2);
            l0 = l0 * sc0 + ps0;
            l1 = l1 * sc1 + ps1;
            m0r = mn0; m1r = mn1;
            #pragma unroll
            for (int nt = 0; nt < 4; nt++) {
                oacc[nt][0] *= sc0; oacc[nt][1] *= sc0;
                oacc[nt][2] *= sc1; oacc[nt][3] *= sc1;
            }
            __syncwarp();
            // O += P V
            #pragma unroll
            for (int ks = 0; ks < 8; ks++) {
                unsigned pa[4];
                pa[0] = Psh[warp][r][ks * 8 + c];
                pa[1] = Psh[warp][r + 8][ks * 8 + c];
                pa[2] = Psh[warp][r][ks * 8 + c + 4];
                pa[3] = Psh[warp][r + 8][ks * 8 + c + 4];
                #pragma unroll
                for (int nt = 0; nt < 4; nt++) {
                    const unsigned vb0 = Vsh[ks * 8 + c][nt * 8 + r];
                    const unsigned vb1 = Vsh[ks * 8 + c + 4][nt * 8 + r];
                    mma_tf32(oacc[nt], pa, vb0, vb1);
                }
            }
        }
    }

    const float inv0 = 1.0f / l0;
    const float inv1 = 1.0f / l1;
    float* Ob = O + (size_t)(b * TSEQ + qbase) * CDIM + h * HS;
    #pragma unroll
    for (int nt = 0; nt < 4; nt++) {
        const int col = nt * 8 + (c << 1);
        Ob[(size_t)r * CDIM + col]           = oacc[nt][0] * inv0;
        Ob[(size_t)r * CDIM + col + 1]       = oacc[nt][1] * inv0;
        Ob[(size_t)(r + 8) * CDIM + col]     = oacc[nt][2] * inv1;
        Ob[(size_t)(r + 8) * CDIM + col + 1] = oacc[nt][3] * inv1;
    }
}

// ----------------------------------------------------------------------------
// Launch
// ----------------------------------------------------------------------------
extern "C" void kernel_launch(void* const* d_in, const int* in_sizes, int n_in,
                              void* d_out, int out_size) {
    const float* x   = (const float*)d_in[0];
    const float* Wq  = (const float*)d_in[1];
    const float* bq  = (const float*)d_in[2];
    const float* Wk  = (const float*)d_in[3];
    const float* bk  = (const float*)d_in[4];
    const float* Wv  = (const float*)d_in[5];
    const float* bv  = (const float*)d_in[6];
    const float* Wo  = (const float*)d_in[7];
    const float* bo  = (const float*)d_in[8];
    const float* W1  = (const float*)d_in[9];
    const float* b1  = (const float*)d_in[10];
    const float* W2  = (const float*)d_in[11];
    const float* b2  = (const float*)d_in[12];
    const float* g1  = (const float*)d_in[13];
    const float* be1 = (const float*)d_in[14];
    const float* g2  = (const float*)d_in[15];
    const float* be2 = (const float*)d_in[16];
    float* out = (float*)d_out;

    float* base = nullptr;
    cudaGetSymbolAddress((void**)&base, g_scratch);
    const size_t SZ = (size_t)MROWS * CDIM;
    float* h1  = base + 0 * SZ;
    float* qb  = base + 1 * SZ;
    float* kb  = base + 2 * SZ;
    float* vb  = base + 3 * SZ;
    float* ob  = base + 4 * SZ;
    float* x1  = base + 5 * SZ;
    float* h2  = base + 6 * SZ;
    float* f1  = base + 7 * SZ;

    const dim3 g_cc(CDIM / 128, MROWS / 128);   // (4, 32)
    const dim3 g_cf(DFF / 128, MROWS / 128);    // (16, 32)

    ln_kernel<<<MROWS, 128>>>(x, g1, be1, h1);
    gemm_tc<1, 0, 0><<<g_cc, 256>>>(h1, Wq, bq, nullptr, qb, MROWS, CDIM, CDIM);
    gemm_tc<1, 0, 0><<<g_cc, 256>>>(h1, Wk, bk, nullptr, kb, MROWS, CDIM, CDIM);
    gemm_tc<1, 0, 0><<<g_cc, 256>>>(h1, Wv, bv, nullptr, vb, MROWS, CDIM, CDIM);
    attn_tc<<<dim3(BATCH * NHEAD, TSEQ / 64), 128>>>(qb, kb, vb, ob);
    gemm_tc<0, 0, 1><<<g_cc, 256>>>(ob, Wo, bo, x, x1, MROWS, CDIM, CDIM);
    ln_kernel<<<MROWS, 128>>>(x1, g2, be2, h2);
    gemm_tc<0, 1, 0><<<g_cf, 256>>>(h2, W1, b1, nullptr, f1, MROWS, DFF, CDIM);
    gemm_tc<0, 0, 1><<<g_cc, 256>>>(f1, W2, b2, x1, out, MROWS, CDIM, DFF);
}

// round 3
// speedup vs baseline: 9.8739x; 2.0668x over previous
#include <cuda_runtime.h>
#include <cuda_fp16.h>
#include <math.h>

#define BATCH  2
#define TSEQ   2048
#define CDIM   512
#define NHEAD  16
#define HS     32
#define DFF    2048
#define MROWS  (BATCH * TSEQ)   // 4096
#define LN_EPS 1e-3f

// fp16 activation scratch: h1(2M) qkv(6M) o(2M) h2(2M) f1(8M) = 20.97M halfs
__device__ __half g_h16[20971520];
// fp16 transposed weights: wqkv(786432) wo(262144) w1(1048576) w2(1048576)
__device__ __half g_w16[3145728];
// fp32: x1 (2M) + combined qkv bias (1536)
__device__ float g_f32[2098688];

// ---------------------------------------------------------------- helpers
__device__ __forceinline__ unsigned s2u(const void* p) {
    return (unsigned)__cvta_generic_to_shared(p);
}
__device__ __forceinline__ void cpa16(void* s, const void* g) {
    asm volatile("cp.async.cg.shared.global [%0], [%1], 16;" :: "r"(s2u(s)), "l"(g));
}
__device__ __forceinline__ void cp_commit() { asm volatile("cp.async.commit_group;"); }
template<int N> __device__ __forceinline__ void cp_wait() {
    asm volatile("cp.async.wait_group %0;" :: "n"(N));
}
__device__ __forceinline__ void ldm_x4(unsigned* d, const void* p) {
    asm volatile("ldmatrix.sync.aligned.m8n8.x4.shared.b16 {%0,%1,%2,%3}, [%4];"
                 : "=r"(d[0]), "=r"(d[1]), "=r"(d[2]), "=r"(d[3]) : "r"(s2u(p)));
}
__device__ __forceinline__ void ldm_x4t(unsigned* d, const void* p) {
    asm volatile("ldmatrix.sync.aligned.m8n8.x4.trans.shared.b16 {%0,%1,%2,%3}, [%4];"
                 : "=r"(d[0]), "=r"(d[1]), "=r"(d[2]), "=r"(d[3]) : "r"(s2u(p)));
}
__device__ __forceinline__ void mma16(float* c, const unsigned* a, unsigned b0, unsigned b1) {
    asm volatile("mma.sync.aligned.m16n8k16.row.col.f32.f16.f16.f32 "
                 "{%0,%1,%2,%3}, {%4,%5,%6,%7}, {%8,%9}, {%0,%1,%2,%3};"
                 : "+f"(c[0]), "+f"(c[1]), "+f"(c[2]), "+f"(c[3])
                 : "r"(a[0]), "r"(a[1]), "r"(a[2]), "r"(a[3]), "r"(b0), "r"(b1));
}
__device__ __forceinline__ unsigned packh2(float a, float b) {
    __half2 h = __floats2half2_rn(a, b);
    return *reinterpret_cast<unsigned*>(&h);
}

// ---------------------------------------------------------------- weight prep
// De-head + transpose Q/K/V weights: out[n][k], n=0..1535, seg=n/512
__global__ void wprep_qkv(const float* __restrict__ Wq, const float* __restrict__ Wk,
                          const float* __restrict__ Wv, __half* __restrict__ out) {
    const int idx = blockIdx.x * 256 + threadIdx.x;   // 786432 total
    const int n = idx >> 9, k = idx & 511;
    const int seg = n >> 9, n2 = n & 511;
    const int h = n2 >> 5, d = n2 & 31;
    const float* W = (seg == 0) ? Wq : (seg == 1) ? Wk : Wv;
    out[idx] = __float2half(W[(h * 512 + k) * 32 + d]);
}
// Transpose+convert plain weight [K][N] fp32 -> [N][K] fp16
__global__ void wprep_t(const float* __restrict__ in, __half* __restrict__ out, int K, int N) {
    __shared__ float tile[32][33];
    const int n0 = blockIdx.x * 32, k0 = blockIdx.y * 32;
    const int tx = threadIdx.x, ty = threadIdx.y;
    #pragma unroll
    for (int i = 0; i < 4; i++)
        tile[ty + i * 8][tx] = in[(size_t)(k0 + ty + i * 8) * N + n0 + tx];
    __syncthreads();
    #pragma unroll
    for (int i = 0; i < 4; i++)
        out[(size_t)(n0 + ty + i * 8) * K + k0 + tx] = __float2half(tile[tx][ty + i * 8]);
}
__global__ void bias_comb(const float* __restrict__ bq, const float* __restrict__ bk,
                          const float* __restrict__ bv, float* __restrict__ out) {
    const int i = threadIdx.x + blockIdx.x * 256;
    if (i < 512) { out[i] = bq[i]; out[512 + i] = bk[i]; out[1024 + i] = bv[i]; }
}

// ---------------------------------------------------------------- LayerNorm -> fp16
__global__ void ln_kernel(const float* __restrict__ x, const float* __restrict__ g,
                          const float* __restrict__ b, __half* __restrict__ out) {
    __shared__ float sh[4];
    const int row = blockIdx.x;
    const int t = threadIdx.x;
    const float4 v = reinterpret_cast<const float4*>(x + (size_t)row * CDIM)[t];

    float s = v.x + v.y + v.z + v.w;
    #pragma unroll
    for (int o = 16; o > 0; o >>= 1) s += __shfl_xor_sync(0xffffffffu, s, o);
    if ((t & 31) == 0) sh[t >> 5] = s;
    __syncthreads();
    const float mu = (sh[0] + sh[1] + sh[2] + sh[3]) * (1.0f / CDIM);
    __syncthreads();

    float d0 = v.x - mu, d1 = v.y - mu, d2 = v.z - mu, d3 = v.w - mu;
    float q = d0*d0 + d1*d1 + d2*d2 + d3*d3;
    #pragma unroll
    for (int o = 16; o > 0; o >>= 1) q += __shfl_xor_sync(0xffffffffu, q, o);
    if ((t & 31) == 0) sh[t >> 5] = q;
    __syncthreads();
    const float var = (sh[0] + sh[1] + sh[2] + sh[3]) * (1.0f / CDIM);
    const float inv = rsqrtf(var + LN_EPS);

    const float4 gv = reinterpret_cast<const float4*>(g)[t];
    const float4 bv = reinterpret_cast<const float4*>(b)[t];
    uint2 o2;
    o2.x = packh2(d0 * inv * gv.x + bv.x, d1 * inv * gv.y + bv.y);
    o2.y = packh2(d2 * inv * gv.z + bv.z, d3 * inv * gv.w + bv.w);
    reinterpret_cast<uint2*>(out + (size_t)row * CDIM)[t] = o2;
}

// ---------------------------------------------------------------- fp16 GEMM
// out[M,N] = A[M,K](fp16) @ W^T[N,K](fp16) + bias(fp32) (+res fp32)(relu?)
// BM=128 BN=128 BK=32, 2-stage cp.async, 256 thr = 8 warps (2m x 4n), warp 64x32.
template<int RELU, int HASRES, int OUT16, int OUT32>
__global__ __launch_bounds__(256, 2)
void gemm_h(const __half* __restrict__ A, const __half* __restrict__ W,
            const float* __restrict__ bias, const float* __restrict__ res,
            float* __restrict__ out32, __half* __restrict__ out16,
            int M, int N, int K) {
    __shared__ __align__(16) __half As[2][128][40];
    __shared__ __align__(16) __half Bs[2][128][40];
    const int tid  = threadIdx.x;
    const int lane = tid & 31;
    const int warp = tid >> 5;
    const int wm = (warp & 1) * 64;
    const int wn = (warp >> 1) * 32;
    const int m0 = blockIdx.y * 128;
    const int n0 = blockIdx.x * 128;
    const int r  = lane >> 2, cq = lane & 3;

    float acc[4][4][4];
    #pragma unroll
    for (int i = 0; i < 4; i++)
        #pragma unroll
        for (int j = 0; j < 4; j++)
            { acc[i][j][0]=0.f; acc[i][j][1]=0.f; acc[i][j][2]=0.f; acc[i][j][3]=0.f; }

    // cp.async indices: 2 chunks each for A and B per thread per stage
    const int ar = tid >> 1;            // rows ar, ar+... chunk = i*256+tid: m=chunk>>2
    (void)ar;
    const int nk = K >> 5;

    auto load_stage = [&](int st, int kk) {
        #pragma unroll
        for (int i = 0; i < 2; i++) {
            const int chunk = i * 256 + tid;
            const int m = chunk >> 2, c4 = (chunk & 3) << 3;
            cpa16(&As[st][m][c4], A + (size_t)(m0 + m) * K + kk + c4);
        }
        #pragma unroll
        for (int i = 0; i < 2; i++) {
            const int chunk = i * 256 + tid;
            const int n = chunk >> 2, c4 = (chunk & 3) << 3;
            cpa16(&Bs[st][n][c4], W + (size_t)(n0 + n) * K + kk + c4);
        }
    };

    load_stage(0, 0);
    cp_commit();

    for (int t = 0; t < nk; t++) {
        if (t + 1 < nk) load_stage((t + 1) & 1, (t + 1) << 5);
        cp_commit();
        cp_wait<1>();
        __syncthreads();
        const int st = t & 1;
        #pragma unroll
        for (int ks = 0; ks < 2; ks++) {
            unsigned a[4][4], bfr[2][4];
            #pragma unroll
            for (int mt = 0; mt < 4; mt++)
                ldm_x4(a[mt], &As[st][wm + mt * 16 + (lane & 15)][ks * 16 + ((lane >> 4) << 3)]);
            #pragma unroll
            for (int np = 0; np < 2; np++)
                ldm_x4(bfr[np], &Bs[st][wn + np * 16 + (lane & 7) + ((lane >> 4) << 3)]
                                     [ks * 16 + (((lane >> 3) & 1) << 3)]);
            #pragma unroll
            for (int mt = 0; mt < 4; mt++) {
                #pragma unroll
                for (int np = 0; np < 2; np++) {
                    mma16(acc[mt][2 * np],     a[mt], bfr[np][0], bfr[np][1]);
                    mma16(acc[mt][2 * np + 1], a[mt], bfr[np][2], bfr[np][3]);
                }
            }
        }
        __syncthreads();
    }

    #pragma unroll
    for (int mt = 0; mt < 4; mt++) {
        #pragma unroll
        for (int nt = 0; nt < 4; nt++) {
            const int row = m0 + wm + mt * 16 + r;
            const int col = n0 + wn + nt * 8 + (cq << 1);
            const float2 bb = *reinterpret_cast<const float2*>(bias + col);
            float v0 = acc[mt][nt][0] + bb.x;
            float v1 = acc[mt][nt][1] + bb.y;
            float v2 = acc[mt][nt][2] + bb.x;
            float v3 = acc[mt][nt][3] + bb.y;
            if (HASRES) {
                const float2 r0v = *reinterpret_cast<const float2*>(res + (size_t)row * N + col);
                const float2 r1v = *reinterpret_cast<const float2*>(res + (size_t)(row + 8) * N + col);
                v0 += r0v.x; v1 += r0v.y; v2 += r1v.x; v3 += r1v.y;
            }
            if (RELU) {
                v0 = fmaxf(v0, 0.f); v1 = fmaxf(v1, 0.f);
                v2 = fmaxf(v2, 0.f); v3 = fmaxf(v3, 0.f);
            }
            if (OUT32) {
                *reinterpret_cast<float2*>(out32 + (size_t)row * N + col) = make_float2(v0, v1);
                *reinterpret_cast<float2*>(out32 + (size_t)(row + 8) * N + col) = make_float2(v2, v3);
            }
            if (OUT16) {
                *reinterpret_cast<unsigned*>(out16 + (size_t)row * N + col) = packh2(v0, v1);
                *reinterpret_cast<unsigned*>(out16 + (size_t)(row + 8) * N + col) = packh2(v2, v3);
            }
        }
    }
}

// ---------------------------------------------------------------- fp16 flash attention
// qkv: [4096][1536] fp16 (q|k|v each 512 cols, col = h*32+d). NO 1/sqrt(hs) scale.
// Grid (B*H, T/64), 128 thr = 4 warps x 16 query rows. 64-key cp.async double-buffered tiles.
__global__ __launch_bounds__(128)
void attn_h(const __half* __restrict__ qkv, __half* __restrict__ O) {
    __shared__ __align__(16) __half Ks[2][64][40];
    __shared__ __align__(16) __half Vs[2][64][40];
    const int bh = blockIdx.x;
    const int b = bh >> 4, h = bh & 15;
    const int warp = threadIdx.x >> 5;
    const int lane = threadIdx.x & 31;
    const int qt = blockIdx.y;
    const int qbase = qt * 64 + warp * 16;
    const int r = lane >> 2, c = lane & 3;

    // Q fragments: 2 ksteps of m16k16
    unsigned qf[2][4];
    const __half* Qb = qkv + (size_t)(b * TSEQ + qbase) * 1536 + h * HS;
    #pragma unroll
    for (int ks = 0; ks < 2; ks++) {
        qf[ks][0] = *reinterpret_cast<const unsigned*>(Qb + (size_t)r * 1536 + ks * 16 + 2 * c);
        qf[ks][1] = *reinterpret_cast<const unsigned*>(Qb + (size_t)(r + 8) * 1536 + ks * 16 + 2 * c);
        qf[ks][2] = *reinterpret_cast<const unsigned*>(Qb + (size_t)r * 1536 + ks * 16 + 8 + 2 * c);
        qf[ks][3] = *reinterpret_cast<const unsigned*>(Qb + (size_t)(r + 8) * 1536 + ks * 16 + 8 + 2 * c);
    }

    float oacc[4][4];
    #pragma unroll
    for (int i = 0; i < 4; i++) { oacc[i][0]=0.f; oacc[i][1]=0.f; oacc[i][2]=0.f; oacc[i][3]=0.f; }
    float m0r = -INFINITY, m1r = -INFINITY, l0 = 0.f, l1 = 0.f;

    const int nT = qt + 1;
    auto load_kv = [&](int st, int j0) {
        #pragma unroll
        for (int i = 0; i < 4; i++) {
            const int chunk = i * 128 + threadIdx.x;          // 512 chunks
            const int arr = chunk >> 8;                        // 0=K 1=V
            const int row = (chunk >> 2) & 63;
            const int c4 = (chunk & 3) << 3;
            const __half* src = qkv + (size_t)(b * TSEQ + j0 + row) * 1536
                                + 512 + arr * 512 + h * HS + c4;
            if (arr == 0) cpa16(&Ks[st][row][c4], src);
            else          cpa16(&Vs[st][row][c4], src);
        }
    };

    load_kv(0, 0);
    cp_commit();

    for (int jt = 0; jt < nT; jt++) {
        if (jt + 1 < nT) load_kv((jt + 1) & 1, (jt + 1) * 64);
        cp_commit();
        cp_wait<1>();
        __syncthreads();
        const int st = jt & 1;
        const int j0 = jt * 64;

        // S = Q K^T (16 x 64), fp32 accum
        float s[8][4];
        #pragma unroll
        for (int nt = 0; nt < 8; nt++) { s[nt][0]=0.f; s[nt][1]=0.f; s[nt][2]=0.f; s[nt][3]=0.f; }
        #pragma unroll
        for (int ks = 0; ks < 2; ks++) {
            #pragma unroll
            for (int np = 0; np < 4; np++) {
                unsigned kb[4];
                ldm_x4(kb, &Ks[st][np * 16 + (lane & 7) + ((lane >> 4) << 3)]
                               [ks * 16 + (((lane >> 3) & 1) << 3)]);
                mma16(s[2 * np],     qf[ks], kb[0], kb[1]);
                mma16(s[2 * np + 1], qf[ks], kb[2], kb[3]);
            }
        }
        // causal mask (only final tile)
        if (jt == qt) {
            #pragma unroll
            for (int nt = 0; nt < 8; nt++) {
                const int key = j0 + nt * 8 + (c << 1);
                if (key     > qbase + r)     s[nt][0] = -INFINITY;
                if (key + 1 > qbase + r)     s[nt][1] = -INFINITY;
                if (key     > qbase + 8 + r) s[nt][2] = -INFINITY;
                if (key + 1 > qbase + 8 + r) s[nt][3] = -INFINITY;
            }
        }
        // online softmax
        float mx0 = -INFINITY, mx1 = -INFINITY;
        #pragma unroll
        for (int nt = 0; nt < 8; nt++) {
            mx0 = fmaxf(mx0, fmaxf(s[nt][0], s[nt][1]));
            mx1 = fmaxf(mx1, fmaxf(s[nt][2], s[nt][3]));
        }
        mx0 = fmaxf(mx0, __shfl_xor_sync(0xffffffffu, mx0, 1));
        mx0 = fmaxf(mx0, __shfl_xor_sync(0xffffffffu, mx0, 2));
        mx1 = fmaxf(mx1, __shfl_xor_sync(0xffffffffu, mx1, 1));
        mx1 = fmaxf(mx1, __shfl_xor_sync(0xffffffffu, mx1, 2));
        const float mn0 = fmaxf(m0r, mx0);
        const float mn1 = fmaxf(m1r, mx1);
        const float sc0 = __expf(m0r - mn0);
        const float sc1 = __expf(m1r - mn1);
        float ps0 = 0.f, ps1 = 0.f;
        #pragma unroll
        for (int nt = 0; nt < 8; nt++) {
            s[nt][0] = __expf(s[nt][0] - mn0);
            s[nt][1] = __expf(s[nt][1] - mn0);
            s[nt][2] = __expf(s[nt][2] - mn1);
            s[nt][3] = __expf(s[nt][3] - mn1);
            ps0 += s[nt][0] + s[nt][1];
            ps1 += s[nt][2] + s[nt][3];
        }
        ps0 += __shfl_xor_sync(0xffffffffu, ps0, 1);
        ps0 += __shfl_xor_sync(0xffffffffu, ps0, 2);
        ps1 += __shfl_xor_sync(0xffffffffu, ps1, 1);
        ps1 += __shfl_xor_sync(0xffffffffu, ps1, 2);
        l0 = l0 * sc0 + ps0;
        l1 = l1 * sc1 + ps1;
        m0r = mn0; m1r = mn1;
        #pragma unroll
        for (int nt = 0; nt < 4; nt++) {
            oacc[nt][0] *= sc0; oacc[nt][1] *= sc0;
            oacc[nt][2] *= sc1; oacc[nt][3] *= sc1;
        }
        // O += P V : P fragments straight from registers
        #pragma unroll
        for (int kt = 0; kt < 4; kt++) {
            unsigned pf[4];
            pf[0] = packh2(s[2 * kt][0],     s[2 * kt][1]);
            pf[1] = packh2(s[2 * kt][2],     s[2 * kt][3]);
            pf[2] = packh2(s[2 * kt + 1][0], s[2 * kt + 1][1]);
            pf[3] = packh2(s[2 * kt + 1][2], s[2 * kt + 1][3]);
            #pragma unroll
            for (int np = 0; np < 2; np++) {
                unsigned vb[4];
                ldm_x4t(vb, &Vs[st][kt * 16 + (lane & 7) + (((lane >> 3) & 1) << 3)]
                                [np * 16 + ((lane >> 4) << 3)]);
                mma16(oacc[2 * np],     pf, vb[0], vb[1]);
                mma16(oacc[2 * np + 1], pf, vb[2], vb[3]);
            }
        }
        __syncthreads();
    }

    const float inv0 = 1.0f / l0;
    const float inv1 = 1.0f / l1;
    __half* Ob = O + (size_t)(b * TSEQ + qbase) * CDIM + h * HS;
    #pragma unroll
    for (int nt = 0; nt < 4; nt++) {
        const int col = nt * 8 + (c << 1);
        *reinterpret_cast<unsigned*>(Ob + (size_t)r * CDIM + col) =
            packh2(oacc[nt][0] * inv0, oacc[nt][1] * inv0);
        *reinterpret_cast<unsigned*>(Ob + (size_t)(r + 8) * CDIM + col) =
            packh2(oacc[nt][2] * inv1, oacc[nt][3] * inv1);
    }
}

// ---------------------------------------------------------------- launch
extern "C" void kernel_launch(void* const* d_in, const int* in_sizes, int n_in,
                              void* d_out, int out_size) {
    const float* x   = (const float*)d_in[0];
    const float* Wq  = (const float*)d_in[1];
    const float* bq  = (const float*)d_in[2];
    const float* Wk  = (const float*)d_in[3];
    const float* bk  = (const float*)d_in[4];
    const float* Wv  = (const float*)d_in[5];
    const float* bv  = (const float*)d_in[6];
    const float* Wo  = (const float*)d_in[7];
    const float* bo  = (const float*)d_in[8];
    const float* W1  = (const float*)d_in[9];
    const float* b1  = (const float*)d_in[10];
    const float* W2  = (const float*)d_in[11];
    const float* b2  = (const float*)d_in[12];
    const float* g1  = (const float*)d_in[13];
    const float* be1 = (const float*)d_in[14];
    const float* g2  = (const float*)d_in[15];
    const float* be2 = (const float*)d_in[16];
    float* out = (float*)d_out;

    __half* hbase = nullptr; __half* wbase = nullptr; float* fbase = nullptr;
    cudaGetSymbolAddress((void**)&hbase, g_h16);
    cudaGetSymbolAddress((void**)&wbase, g_w16);
    cudaGetSymbolAddress((void**)&fbase, g_f32);

    __half* h1   = hbase + 0;
    __half* qkv  = hbase + 2097152;
    __half* o16  = hbase + 8388608;
    __half* h2   = hbase + 10485760;
    __half* f1   = hbase + 12582912;
    __half* Wc   = wbase + 0;          // [1536][512]
    __half* Wo16 = wbase + 786432;     // [512][512]
    __half* W116 = wbase + 1048576;    // [2048][512]
    __half* W216 = wbase + 2097152;    // [512][2048]
    float*  x1   = fbase + 0;
    float*  bqkv = fbase + 2097152;

    // weight prep (graph-captured, runs each replay; ~15us)
    wprep_qkv<<<3072, 256>>>(Wq, Wk, Wv, Wc);
    wprep_t<<<dim3(16, 16), dim3(32, 8)>>>(Wo, Wo16, 512, 512);
    wprep_t<<<dim3(64, 16), dim3(32, 8)>>>(W1, W116, 512, 2048);
    wprep_t<<<dim3(16, 64), dim3(32, 8)>>>(W2, W216, 2048, 512);
    bias_comb<<<2, 256>>>(bq, bk, bv, bqkv);

    ln_kernel<<<MROWS, 128>>>(x, g1, be1, h1);
    // fused QKV: N=1536
    gemm_h<0, 0, 1, 0><<<dim3(12, 32), 256>>>(h1, Wc, bqkv, nullptr, nullptr, qkv,
                                              MROWS, 1536, CDIM);
    attn_h<<<dim3(BATCH * NHEAD, TSEQ / 64), 128>>>(qkv, o16);
    gemm_h<0, 1, 0, 1><<<dim3(4, 32), 256>>>(o16, Wo16, bo, x, x1, nullptr,
                                             MROWS, CDIM, CDIM);
    ln_kernel<<<MROWS, 128>>>(x1, g2, be2, h2);
    gemm_h<1, 0, 1, 0><<<dim3(16, 32), 256>>>(h2, W116, b1, nullptr, nullptr, f1,
                                              MROWS, DFF, CDIM);
    gemm_h<0, 1, 0, 1><<<dim3(4, 32), 256>>>(f1, W216, b2, x1, out, nullptr,
                                             MROWS, CDIM, DFF);
}